// round 2
// baseline (speedup 1.0000x reference)
#include <cuda_runtime.h>
#include <cuda_bf16.h>
#include <cstdint>

// DomainGate: T=8192 tokens, E=16 experts, capacity C = ceil(T/E) = 512.
// Outputs packed in d_out (float32): [l_aux (1)] [combine1_sec T*E*C] [dispatch_mask T*E*C].
// Result is one-hot sparse (<= T nonzeros out of 134M elements):
//   1) memset entire output to 0 (l_aux = 0 for free)
//   2) tiny ballot-scan kernel computes each token's capacity slot
//   3) scatter kernel writes <= T ones.
// NOTE: mask (jax bool) arrives promoted to int32 -> read as int, nonzero = padded.
//       (Nonzero test also handles a float32 promotion correctly.)

#define NUM_EXPERTS 16

// scratch: per-token capacity slot (-1 if dropped/padded). T is 8192; headroom to 32768.
__device__ int g_pos[1 << 15];

// One CTA, one warp per expert. Warp e scans all tokens with ballots and
// assigns a stable position (rank among kept tokens of expert e).
__global__ void __launch_bounds__(NUM_EXPERTS * 32, 1)
pos_kernel(const int* __restrict__ dom, const int* __restrict__ mask,
           int T, int capacity) {
    const int e    = threadIdx.x >> 5;   // expert handled by this warp
    const int lane = threadIdx.x & 31;

    int count = 0;  // kept tokens of expert e scanned so far
    for (int base = 0; base < T; base += 32) {
        const int t = base + lane;
        int d = -1;
        bool padded = true;
        if (t < T) {
            d = dom[t];
            padded = (mask[t] != 0);   // int32 (or float32-bits) nonzero = masked out
        }
        const bool match = (d == e) && !padded;
        const unsigned bal = __ballot_sync(0xffffffffu, match);
        const int p = count + __popc(bal & ((1u << lane) - 1u));
        if (t < T && d == e) {
            // exactly one warp (this one) owns token t -> no write conflicts
            g_pos[t] = (match && p < capacity) ? p : -1;
        }
        count += __popc(bal);
    }
}

// Scatter ones into the zeroed output. dispatch either as f32 (disp_f) or as
// raw bool bytes (disp_b); at most one of them is non-null.
__global__ void scatter_kernel(const int* __restrict__ dom, int T, int capacity,
                               float* __restrict__ combine,
                               float* __restrict__ disp_f,
                               unsigned char* __restrict__ disp_b) {
    const int t = blockIdx.x * blockDim.x + threadIdx.x;
    if (t >= T) return;
    const int p = g_pos[t];
    if (p < 0) return;
    const size_t off = (size_t)t * NUM_EXPERTS * capacity
                     + (size_t)dom[t] * capacity + p;
    combine[off] = 1.0f;
    if (disp_f) disp_f[off] = 1.0f;
    if (disp_b) disp_b[off] = 1;
}

extern "C" void kernel_launch(void* const* d_in, const int* in_sizes, int n_in,
                              void* d_out, int out_size) {
    // inputs: [0] input f32 [T,D] (unused), [1] domain_ids i32 [T], [2] mask (bool->i32) [T]
    const int* dom  = (const int*)d_in[1];
    const int* mask = (const int*)d_in[2];
    const int T = in_sizes[1];
    const int C = (T + NUM_EXPERTS - 1) / NUM_EXPERTS;
    const size_t TEC = (size_t)T * NUM_EXPERTS * C;

    float* out = (float*)d_out;

    // Resolve the packed-output layout from out_size (element count of output dtype).
    // Expected: [l_aux (1 f32)] [combine TEC f32] [dispatch TEC f32]
    float*         combine = out + 1;
    float*         disp_f  = out + 1 + TEC;
    unsigned char* disp_b  = nullptr;
    size_t total_bytes = (size_t)out_size * sizeof(float);

    const size_t sz_float_all   = 1 + 2 * TEC;                 // all f32
    const size_t sz_bool_packed = 1 + TEC + (TEC + 3) / 4;     // dispatch as bytes
    const size_t sz_no_laux     = 2 * TEC;                     // no scalar

    if ((size_t)out_size == sz_float_all) {
        // defaults above
    } else if ((size_t)out_size == sz_bool_packed) {
        disp_f = nullptr;
        disp_b = (unsigned char*)(out + 1 + TEC);
    } else if ((size_t)out_size == sz_no_laux) {
        combine = out;
        disp_f  = out + TEC;
    }
    // else: keep defaults (float layout with l_aux).

    // 1) zero the whole output (covers l_aux=0 and all non-selected slots)
    cudaMemsetAsync(d_out, 0, total_bytes, 0);

    // 2) positions (1 CTA, 16 warps)
    pos_kernel<<<1, NUM_EXPERTS * 32>>>(dom, mask, T, C);

    // 3) scatter <= T ones
    scatter_kernel<<<(T + 255) / 256, 256>>>(dom, T, C, combine, disp_f, disp_b);
}